// round 2
// baseline (speedup 1.0000x reference)
#include <cuda_runtime.h>
#include <cuda_bf16.h>

// B=4, H=16, L=8192, D=64
#define BH_    64
#define H_     16
#define L_     8192
#define D_     64
#define PPW_   8                 // positions per warp
#define WPB_   8                 // warps per block
#define TILE_  (PPW_ * WPB_)     // 64 positions per block
#define TILES_ 128               // L_ / TILE_  (chain length per bh)
#define NBLK_  (BH_ * TILES_)    // 8192 blocks
#define EPS_   1e-6f

// Per-(tile, channel) scan descriptor: hi32 = flag (0 none / 1 aggregate /
// 2 inclusive), lo32 = float bits. Single 8-byte word => atomic publish,
// no fences required.
__device__ unsigned long long g_desc[(size_t)NBLK_ * 128];

__device__ __forceinline__ float phi(float x) {
    return x > 0.0f ? x + 1.0f : __expf(x);
}

__global__ void la_reset() {
    size_t i = (size_t)blockIdx.x * blockDim.x + threadIdx.x;
    g_desc[i] = 0ULL;
}

// ---------------------------------------------------------------------------
// Single-pass scan + output. Each block owns one 64-position tile of one (b,h)
// chain. Warp w handles positions [w*8, w*8+8); lane owns channels 2*lane,
// 2*lane+1 of both the k-state (64 ch) and kv-state (64 ch).
// ---------------------------------------------------------------------------
__global__ void __launch_bounds__(256) la_scan(
    const float* __restrict__ qp, const float* __restrict__ kp,
    const float* __restrict__ vp, const float* __restrict__ mp,
    float* __restrict__ op)
{
    __shared__ float s_scan[WPB_][128];   // per-warp sums -> exclusive prefixes
    __shared__ float s_chain[128];        // exclusive chain prefix for this tile

    const int t    = threadIdx.x;
    const int w    = t >> 5;
    const int lane = t & 31;
    const int blk  = blockIdx.x;
    const int bh   = blk >> 7;            // / TILES_
    const int tile = blk & (TILES_ - 1);
    const int b    = bh >> 4;             // / H_
    const int l0   = tile * TILE_ + w * PPW_;
    const size_t base = ((size_t)bh * L_ + l0) * D_ + lane * 2;

    // ---- Phase A: load k,v once; keep per-position contributions in regs ----
    float fk0[PPW_], fk1[PPW_], kv0[PPW_], kv1[PPW_];
    float sk0 = 0.f, sk1 = 0.f, sv0 = 0.f, sv1 = 0.f;
    #pragma unroll
    for (int i = 0; i < PPW_; ++i) {
        float2 kk = *(const float2*)(kp + base + i * D_);
        float2 vv = *(const float2*)(vp + base + i * D_);
        float  m  = mp[b * L_ + l0 + i];
        float a0 = phi(kk.x) * m, a1 = phi(kk.y) * m;
        float c0 = a0 * (vv.x * m), c1 = a1 * (vv.y * m);
        fk0[i] = a0; fk1[i] = a1; kv0[i] = c0; kv1[i] = c1;
        sk0 += a0; sk1 += a1; sv0 += c0; sv1 += c1;
    }
    *(float2*)&s_scan[w][2 * lane]      = make_float2(sk0, sk1);
    *(float2*)&s_scan[w][64 + 2 * lane] = make_float2(sv0, sv1);
    __syncthreads();

    // ---- Phase B: in-block scan over warps + decoupled lookback ----
    if (t < 128) {
        const int c = t;                  // flat channel index [0,128)
        float run = 0.f;
        #pragma unroll
        for (int g = 0; g < WPB_; ++g) {
            float x = s_scan[g][c];
            s_scan[g][c] = run;           // exclusive per-warp prefix
            run += x;
        }                                 // run = tile total
        volatile unsigned long long* desc = g_desc;
        float chain = 0.f;
        const size_t my = (size_t)blk * 128 + c;
        if (tile == 0) {
            desc[my] = (2ULL << 32) | (unsigned long long)__float_as_uint(run);
        } else {
            desc[my] = (1ULL << 32) | (unsigned long long)__float_as_uint(run);
            int p = blk - 1;
            for (;;) {
                unsigned long long d;
                do { d = desc[(size_t)p * 128 + c]; } while ((unsigned)(d >> 32) == 0u);
                chain += __uint_as_float((unsigned)(d & 0xffffffffu));
                if ((unsigned)(d >> 32) == 2u) break;
                --p;
            }
            desc[my] = (2ULL << 32) |
                       (unsigned long long)__float_as_uint(chain + run);
        }
        s_chain[c] = chain;
    }
    __syncthreads();

    // ---- Phase C: finish scan in registers, compute z and output ----
    float2 pk  = make_float2(s_chain[2 * lane]     + s_scan[w][2 * lane],
                             s_chain[2 * lane + 1] + s_scan[w][2 * lane + 1]);
    float2 pkv = make_float2(s_chain[64 + 2 * lane]     + s_scan[w][64 + 2 * lane],
                             s_chain[64 + 2 * lane + 1] + s_scan[w][64 + 2 * lane + 1]);

    #pragma unroll
    for (int i = 0; i < PPW_; ++i) {
        pk.x  += fk0[i]; pk.y  += fk1[i];
        pkv.x += kv0[i]; pkv.y += kv1[i];
        float2 qq = *(const float2*)(qp + base + i * D_);
        float  m  = mp[b * L_ + l0 + i];
        float q0 = phi(qq.x), q1 = phi(qq.y);
        float z = q0 * pk.x + q1 * pk.y;
        z += __shfl_xor_sync(0xffffffffu, z, 16);
        z += __shfl_xor_sync(0xffffffffu, z, 8);
        z += __shfl_xor_sync(0xffffffffu, z, 4);
        z += __shfl_xor_sync(0xffffffffu, z, 2);
        z += __shfl_xor_sync(0xffffffffu, z, 1);
        z = (z + EPS_) * m;
        float rz = 1.0f / z;
        float2 o = make_float2(q0 * pkv.x * rz, q1 * pkv.y * rz);
        *(float2*)(op + base + i * D_) = o;
    }
}

// ---------------------------------------------------------------------------
extern "C" void kernel_launch(void* const* d_in, const int* in_sizes, int n_in,
                              void* d_out, int out_size)
{
    const float* q = (const float*)d_in[0];
    const float* k = (const float*)d_in[1];
    const float* v = (const float*)d_in[2];
    const float* m = (const float*)d_in[3];
    float* out = (float*)d_out;

    la_reset<<<(NBLK_ * 128) / 256, 256>>>();
    la_scan<<<NBLK_, 256>>>(q, k, v, m, out);
}

// round 3
// speedup vs baseline: 1.2077x; 1.2077x over previous
#include <cuda_runtime.h>
#include <cuda_bf16.h>

// B=4, H=16, L=8192, D=64
#define BH_   64
#define H_    16
#define L_    8192
#define D_    64
#define S_    32        // positions per subchunk
#define NSUB_ 256       // L_ / S_
#define EPS_  1e-6f

// Scratch: per-(bh, subchunk) [ sum_k(64) | sum_kv(64) ]
__device__ float g_sums  [BH_ * NSUB_ * 128];
__device__ float g_prefix[BH_ * NSUB_ * 128];

__device__ __forceinline__ float phi(float x) {
    return x > 0.0f ? x + 1.0f : __expf(x);
}

// ---------------------------------------------------------------------------
// Pass 1: per-subchunk sums of masked phi(k) and masked phi(k)*v.
// Thread handles (subchunk, d4-quad). Loads explicitly front-batched in
// 8-position rounds (16x LDG.128 + 2x mask float4 in flight).
// ---------------------------------------------------------------------------
__global__ void __launch_bounds__(256) la_pass1(
    const float* __restrict__ kp, const float* __restrict__ vp,
    const float* __restrict__ mp)
{
    const int t    = threadIdx.x;
    const int d4   = t & 15;
    const int subL = t >> 4;
    const int blk  = blockIdx.x;
    const int bh   = blk >> 4;
    const int sub  = ((blk & 15) << 4) | subL;
    const int b    = bh >> 4;
    const int l0   = sub * S_;
    const size_t base = ((size_t)bh * L_ + l0) * D_ + d4 * 4;
    const float* mrow = mp + b * L_ + l0;

    float4 sk  = make_float4(0.f, 0.f, 0.f, 0.f);
    float4 skv = make_float4(0.f, 0.f, 0.f, 0.f);

    #pragma unroll 1
    for (int gb = 0; gb < 4; ++gb) {
        float4 kk[8], vv[8];
        float4 ma = *(const float4*)(mrow + gb * 8);
        float4 mb = *(const float4*)(mrow + gb * 8 + 4);
        #pragma unroll
        for (int j = 0; j < 8; ++j) {
            const size_t off = base + (size_t)(gb * 8 + j) * D_;
            kk[j] = *(const float4*)(kp + off);
            vv[j] = *(const float4*)(vp + off);
        }
        float mm[8] = {ma.x, ma.y, ma.z, ma.w, mb.x, mb.y, mb.z, mb.w};
        #pragma unroll
        for (int j = 0; j < 8; ++j) {
            float mj = mm[j];
            float a0 = phi(kk[j].x) * mj, a1 = phi(kk[j].y) * mj,
                  a2 = phi(kk[j].z) * mj, a3 = phi(kk[j].w) * mj;
            sk.x += a0; sk.y += a1; sk.z += a2; sk.w += a3;
            skv.x += a0 * (vv[j].x * mj); skv.y += a1 * (vv[j].y * mj);
            skv.z += a2 * (vv[j].z * mj); skv.w += a3 * (vv[j].w * mj);
        }
    }

    float* o = g_sums + ((size_t)bh * NSUB_ + sub) * 128;
    *(float4*)(o + d4 * 4)      = sk;
    *(float4*)(o + 64 + d4 * 4) = skv;
}

// ---------------------------------------------------------------------------
// Pass 2: exclusive prefix over 256 subchunks per (bh, channel).
// 1024 threads/block: (c = t&127, seg = t>>7). Each thread scans 32 subchunks
// staged in registers; segment totals combined via smem. One DRAM round trip.
// ---------------------------------------------------------------------------
__global__ void __launch_bounds__(1024) la_pass2()
{
    __shared__ float s_tot[8][128];
    const int bh  = blockIdx.x;
    const int c   = threadIdx.x & 127;
    const int seg = threadIdx.x >> 7;
    const size_t base = (size_t)bh * NSUB_ * 128 + c;

    float vals[32];
    #pragma unroll
    for (int j = 0; j < 32; ++j)
        vals[j] = g_sums[base + (size_t)(seg * 32 + j) * 128];

    float run = 0.f;
    #pragma unroll
    for (int j = 0; j < 32; ++j) { float x = vals[j]; vals[j] = run; run += x; }
    s_tot[seg][c] = run;
    __syncthreads();

    float off = 0.f;
    #pragma unroll
    for (int s = 0; s < 7; ++s)
        if (s < seg) off += s_tot[s][c];

    #pragma unroll
    for (int j = 0; j < 32; ++j)
        g_prefix[base + (size_t)(seg * 32 + j) * 128] = off + vals[j];
}

// ---------------------------------------------------------------------------
// Pass 3: finish scan within each subchunk, compute z (4x shfl over 16-lane
// group) and output. Loads front-batched in 4-position rounds.
// ---------------------------------------------------------------------------
__global__ void __launch_bounds__(256) la_pass3(
    const float* __restrict__ qp, const float* __restrict__ kp,
    const float* __restrict__ vp, const float* __restrict__ mp,
    float* __restrict__ op)
{
    const int t    = threadIdx.x;
    const int d4   = t & 15;
    const int subL = t >> 4;
    const int blk  = blockIdx.x;
    const int bh   = blk >> 4;
    const int sub  = ((blk & 15) << 4) | subL;
    const int b    = bh >> 4;
    const int l0   = sub * S_;
    const size_t base = ((size_t)bh * L_ + l0) * D_ + d4 * 4;
    const float* mrow = mp + b * L_ + l0;

    const float* pr = g_prefix + ((size_t)bh * NSUB_ + sub) * 128;
    float4 pk  = *(const float4*)(pr + d4 * 4);
    float4 pkv = *(const float4*)(pr + 64 + d4 * 4);

    #pragma unroll 1
    for (int gb = 0; gb < 8; ++gb) {
        float4 kk[4], vv[4], qq[4];
        float4 m4 = *(const float4*)(mrow + gb * 4);
        #pragma unroll
        for (int j = 0; j < 4; ++j) {
            const size_t off = base + (size_t)(gb * 4 + j) * D_;
            kk[j] = *(const float4*)(kp + off);
            vv[j] = *(const float4*)(vp + off);
            qq[j] = *(const float4*)(qp + off);
        }
        float mm[4] = {m4.x, m4.y, m4.z, m4.w};
        #pragma unroll
        for (int j = 0; j < 4; ++j) {
            float mj = mm[j];
            float a0 = phi(kk[j].x) * mj, a1 = phi(kk[j].y) * mj,
                  a2 = phi(kk[j].z) * mj, a3 = phi(kk[j].w) * mj;
            pk.x += a0; pk.y += a1; pk.z += a2; pk.w += a3;
            pkv.x += a0 * (vv[j].x * mj); pkv.y += a1 * (vv[j].y * mj);
            pkv.z += a2 * (vv[j].z * mj); pkv.w += a3 * (vv[j].w * mj);

            float q0 = phi(qq[j].x), q1 = phi(qq[j].y),
                  q2 = phi(qq[j].z), q3 = phi(qq[j].w);

            float z = q0 * pk.x + q1 * pk.y + q2 * pk.z + q3 * pk.w;
            z += __shfl_xor_sync(0xffffffffu, z, 8);
            z += __shfl_xor_sync(0xffffffffu, z, 4);
            z += __shfl_xor_sync(0xffffffffu, z, 2);
            z += __shfl_xor_sync(0xffffffffu, z, 1);
            z = (z + EPS_) * mj;
            float rz = 1.0f / z;

            float4 o;
            o.x = q0 * pkv.x * rz; o.y = q1 * pkv.y * rz;
            o.z = q2 * pkv.z * rz; o.w = q3 * pkv.w * rz;
            *(float4*)(op + base + (size_t)(gb * 4 + j) * D_) = o;
        }
    }
}

// ---------------------------------------------------------------------------
extern "C" void kernel_launch(void* const* d_in, const int* in_sizes, int n_in,
                              void* d_out, int out_size)
{
    const float* q = (const float*)d_in[0];
    const float* k = (const float*)d_in[1];
    const float* v = (const float*)d_in[2];
    const float* m = (const float*)d_in[3];
    float* out = (float*)d_out;

    la_pass1<<<BH_ * (NSUB_ / 16), 256>>>(k, v, m);
    la_pass2<<<BH_, 1024>>>();
    la_pass3<<<BH_ * (NSUB_ / 16), 256>>>(q, k, v, m, out);
}

// round 4
// speedup vs baseline: 1.3599x; 1.1261x over previous
#include <cuda_runtime.h>
#include <cuda_bf16.h>

// B=4, H=16, L=8192, D=64
#define BH_    64
#define H_     16
#define L_     8192
#define D_     64
#define TILE_  256                 // positions per tile (block)
#define NT_    32                  // tiles per (b,h) chain
#define NBLK_  (BH_ * NT_)         // 2048
#define EPS_   1e-6f

// Decoupled-lookback state. flag: 0 = none, 1 = aggregate, 2 = inclusive.
__device__ int   g_ticket;
__device__ int   g_flag[NBLK_];
__device__ float g_aggr[(size_t)NBLK_ * 256];   // [128 k-sum | 128 kv-sum]
__device__ float g_incl[(size_t)NBLK_ * 256];

__device__ __forceinline__ float phi(float x) {
    return x > 0.0f ? x + 1.0f : __expf(x);
}

__global__ void la_reset() {
    int i = blockIdx.x * blockDim.x + threadIdx.x;
    if (i < NBLK_) g_flag[i] = 0;
    if (i == 0) g_ticket = 0;
}

// ---------------------------------------------------------------------------
// Fused single-pass: per tile, compute group sums (phase A), intra-tile scan,
// single-flag decoupled lookback across the 32-tile chain, then recompute the
// scan in registers with the chain prefix and emit output (phase C, k/v from L2).
// Thread map: g = t>>4 owns positions [g*16, g*16+16); d4 = t&15 owns channel
// quad d4*4..d4*4+3.
// ---------------------------------------------------------------------------
__global__ void __launch_bounds__(256) la_fused(
    const float* __restrict__ qp, const float* __restrict__ kp,
    const float* __restrict__ vp, const float* __restrict__ mp,
    float* __restrict__ op)
{
    __shared__ float s_k [16][128];   // group sums -> exclusive group prefixes
    __shared__ float s_kv[16][128];
    __shared__ float s_tot[256];      // tile totals   [k | kv]
    __shared__ float s_chain[256];    // chain prefix  [k | kv]
    __shared__ int   s_tile, s_msg;

    const int t = threadIdx.x;
    if (t == 0) s_tile = atomicAdd(&g_ticket, 1);
    __syncthreads();
    const int tile = s_tile;
    const int bh   = tile & (BH_ - 1);     // chain-interleaved ticket mapping
    const int ti   = tile >> 6;
    const int b    = bh >> 4;
    const int g    = t >> 4;
    const int d4   = t & 15;
    const int l0   = ti * TILE_ + g * 16;
    const size_t base = ((size_t)bh * L_ + l0) * D_ + d4 * 4;
    const float* mrow = mp + b * L_ + l0;

    // ---- Phase A: group sums of masked phi(k), phi(k)*v ----
    float4 sk  = make_float4(0.f, 0.f, 0.f, 0.f);
    float4 skv = make_float4(0.f, 0.f, 0.f, 0.f);
    #pragma unroll 4
    for (int i = 0; i < 16; ++i) {
        float4 kk = *(const float4*)(kp + base + (size_t)i * D_);
        float4 vv = *(const float4*)(vp + base + (size_t)i * D_);
        float  m  = mrow[i];
        float a0 = phi(kk.x) * m, a1 = phi(kk.y) * m,
              a2 = phi(kk.z) * m, a3 = phi(kk.w) * m;
        sk.x += a0; sk.y += a1; sk.z += a2; sk.w += a3;
        skv.x += a0 * (vv.x * m); skv.y += a1 * (vv.y * m);
        skv.z += a2 * (vv.z * m); skv.w += a3 * (vv.w * m);
    }
    *(float4*)&s_k [g][d4 * 4] = sk;
    *(float4*)&s_kv[g][d4 * 4] = skv;
    __syncthreads();

    // ---- Intra-tile scan over the 16 groups (t<128: k, t>=128: kv) ----
    {
        float run = 0.f;
        if (t < 128) {
            const int c = t;
            #pragma unroll
            for (int g2 = 0; g2 < 16; ++g2) {
                float x = s_k[g2][c]; s_k[g2][c] = run; run += x;
            }
        } else {
            const int c = t - 128;
            #pragma unroll
            for (int g2 = 0; g2 < 16; ++g2) {
                float x = s_kv[g2][c]; s_kv[g2][c] = run; run += x;
            }
        }
        s_tot[t] = run;
        // Publish aggregate
        if (ti > 0) g_aggr[(size_t)tile * 256 + t] = run;
    }
    __syncthreads();
    if (ti > 0) {
        __threadfence();
        if (t == 0) atomicExch(&g_flag[tile], 1);
    }

    // ---- Decoupled lookback ----
    s_chain[t] = 0.f;
    if (ti > 0) {
        volatile int* vf = (volatile int*)g_flag;
        int p = tile - BH_;
        for (;;) {
            if (t == 0) {
                int f;
                while ((f = vf[p]) == 0) __nanosleep(64);
                s_msg = f;
            }
            __syncthreads();
            const int f = s_msg;
            __threadfence();   // acquire: order payload reads after flag
            if (f == 2) {
                s_chain[t] += g_incl[(size_t)p * 256 + t];
                break;
            }
            s_chain[t] += g_aggr[(size_t)p * 256 + t];
            p -= BH_;
            __syncthreads();
        }
    }
    __syncthreads();

    // ---- Publish inclusive ----
    g_incl[(size_t)tile * 256 + t] = s_chain[t] + s_tot[t];
    __syncthreads();
    __threadfence();
    if (t == 0) atomicExch(&g_flag[tile], 2);

    // ---- Phase C: re-scan own positions from L2, compute z and output ----
    float4 pk, pkv;
    {
        float4 ck  = *(const float4*)&s_chain[d4 * 4];
        float4 ckv = *(const float4*)&s_chain[128 + d4 * 4];
        float4 ek  = *(const float4*)&s_k [g][d4 * 4];
        float4 ekv = *(const float4*)&s_kv[g][d4 * 4];
        pk  = make_float4(ck.x + ek.x,  ck.y + ek.y,  ck.z + ek.z,  ck.w + ek.w);
        pkv = make_float4(ckv.x + ekv.x, ckv.y + ekv.y,
                          ckv.z + ekv.z, ckv.w + ekv.w);
    }

    #pragma unroll 4
    for (int i = 0; i < 16; ++i) {
        const size_t off = base + (size_t)i * D_;
        float4 kk = *(const float4*)(kp + off);
        float4 vv = *(const float4*)(vp + off);
        float4 qq = *(const float4*)(qp + off);
        float  m  = mrow[i];

        float a0 = phi(kk.x) * m, a1 = phi(kk.y) * m,
              a2 = phi(kk.z) * m, a3 = phi(kk.w) * m;
        pk.x += a0; pk.y += a1; pk.z += a2; pk.w += a3;
        pkv.x += a0 * (vv.x * m); pkv.y += a1 * (vv.y * m);
        pkv.z += a2 * (vv.z * m); pkv.w += a3 * (vv.w * m);

        float q0 = phi(qq.x), q1 = phi(qq.y),
              q2 = phi(qq.z), q3 = phi(qq.w);

        float z = q0 * pk.x + q1 * pk.y + q2 * pk.z + q3 * pk.w;
        z += __shfl_xor_sync(0xffffffffu, z, 8);
        z += __shfl_xor_sync(0xffffffffu, z, 4);
        z += __shfl_xor_sync(0xffffffffu, z, 2);
        z += __shfl_xor_sync(0xffffffffu, z, 1);
        z = (z + EPS_) * m;
        float rz = 1.0f / z;

        float4 o;
        o.x = q0 * pkv.x * rz; o.y = q1 * pkv.y * rz;
        o.z = q2 * pkv.z * rz; o.w = q3 * pkv.w * rz;
        *(float4*)(op + off) = o;
    }
}

// ---------------------------------------------------------------------------
extern "C" void kernel_launch(void* const* d_in, const int* in_sizes, int n_in,
                              void* d_out, int out_size)
{
    const float* q = (const float*)d_in[0];
    const float* k = (const float*)d_in[1];
    const float* v = (const float*)d_in[2];
    const float* m = (const float*)d_in[3];
    float* out = (float*)d_out;

    la_reset<<<(NBLK_ + 255) / 256, 256>>>();
    la_fused<<<NBLK_, 256>>>(q, k, v, m, out);
}